// round 8
// baseline (speedup 1.0000x reference)
#include <cuda_runtime.h>
#include <cuda_fp16.h>
#include <math.h>
#include <cstdint>

// Problem constants (fixed by the dataset)
constexpr int Bn = 4096, Tn = 32, Xn = 256, Hn = 256, Zn = 256, Gn = 128, Yn = 2;
constexpr int BT = Bn * Tn; // 131072

#define DI __device__ __forceinline__

DI uint32_t smem_u32(const void* p) {
    uint32_t a;
    asm("{ .reg .u64 t; cvta.to.shared.u64 t, %1; cvt.u32.u64 %0, t; }" : "=r"(a) : "l"(p));
    return a;
}
DI float sigf(float x) { return 1.0f / (1.0f + expf(-x)); }

DI void ldm_x4(uint32_t r[4], uint32_t addr) {
    asm volatile("ldmatrix.sync.aligned.m8n8.x4.shared.b16 {%0,%1,%2,%3}, [%4];"
                 : "=r"(r[0]), "=r"(r[1]), "=r"(r[2]), "=r"(r[3]) : "r"(addr));
}
DI void mma_f16(float d[4], const uint32_t a[4], const uint32_t b[2]) {
    asm volatile(
        "mma.sync.aligned.m16n8k16.row.col.f32.f16.f16.f32 "
        "{%0,%1,%2,%3}, {%4,%5,%6,%7}, {%8,%9}, {%0,%1,%2,%3};"
        : "+f"(d[0]), "+f"(d[1]), "+f"(d[2]), "+f"(d[3])
        : "r"(a[0]), "r"(a[1]), "r"(a[2]), "r"(a[3]), "r"(b[0]), "r"(b[1]));
}
DI void cp16(uint32_t dst, const void* src) {
    asm volatile("cp.async.cg.shared.global [%0], [%1], 16;" :: "r"(dst), "l"(src));
}
#define CP_COMMIT() asm volatile("cp.async.commit_group;" ::: "memory")
#define CP_WAIT(n)  asm volatile("cp.async.wait_group %0;" :: "n"(n) : "memory")

// write fp32 value as fp16 hi/lo pair into a slab [row][512] = [hi(256)|lo(256)]
DI void slab_write(__half* slab, size_t row, int col, float v) {
    __half h = __float2half_rn(v);
    slab[row * 512 + col]       = h;
    slab[row * 512 + 256 + col] = __float2half_rn(v - __half2float(h));
}

// ============================ static device scratch ============================
__device__ float g_AX [131072 * 1280];          // x-projections f32: [r,u,h,zp,zq]
__device__ float g_U  [4096 * 256];
__device__ float g_HD [4096 * 1024];            // [mu_p | lp | mu_q | lq]
__device__ float g_Hf [2 * 4096 * 256];         // f32 h state (prev/next)
__device__ float g_G  [131072 * 128];
// fp16 hi/lo slabs: [row][512] = [hi|lo]
__device__ __align__(16) __half g_Xs  [(size_t)131072 * 512];
__device__ __align__(16) __half g_Hseq[(size_t)131072 * 512];
__device__ __align__(16) __half g_Zseq[(size_t)131072 * 512];
__device__ __align__(16) __half g_Hst [2 * 4096 * 512];
__device__ __align__(16) __half g_Zst [2 * 4096 * 512];
__device__ __align__(16) __half g_RH  [4096 * 512];
__device__ __align__(16) __half g_HZP [4096 * 512];
__device__ __align__(16) __half g_HZQ [4096 * 512];
// prepacked weights: fp16 hi only, transposed, [N][K] K-major
constexpr size_t O1 = 0;                  // [1280][256]
constexpr size_t O2 = O1 + 1280 * 256;    // [512][512]
constexpr size_t O3 = O2 + 512 * 512;     // [256][512]
constexpr size_t O4 = O3 + 256 * 512;     // [512][256]
constexpr size_t O5 = O4 + 512 * 256;     // [1024][256]
constexpr size_t O6 = O5 + 1024 * 256;    // [128][768]
constexpr size_t WTOT = O6 + 128 * 768;
__device__ __align__(16) __half g_Wp[WTOT];

// ============================ A descriptor ============================
struct ADesc { const __half* s0[3]; const __half* s1[3]; };

// ============================ Epilogues ============================
struct EP_AX {
    float* AX; const float* bias[5]; const float* yph; const float* WzqY;
    DI void operator()(int row, int col, float acc) const {
        int seg = col >> 8, c = col & 255;
        float v = acc + bias[seg][c];
        if (seg == 4)
            v += yph[(size_t)row * 2] * WzqY[c] + yph[(size_t)row * 2 + 1] * WzqY[256 + c];
        AX[(size_t)row * 1280 + col] = v;
    }
};
struct EP_RU { // r -> RH slab (r*h_prev), u -> f32 U
    const float* AX; const float* hpf; float* U; __half* RH; int t;
    DI void operator()(int b, int col, float acc) const {
        size_t bt = (size_t)b * Tn + t;
        float pre = acc + AX[bt * 1280 + col];
        if (col < 256) {
            float r = sigf(pre);
            slab_write(RH, b, col, r * hpf[b * 256 + col]);
        } else {
            U[b * 256 + col - 256] = sigf(pre);
        }
    }
};
struct EP_H {
    const float* AX; const float* U; const float* hpf; float* hnf;
    __half* Hst; __half* Hseq; int t;
    DI void operator()(int b, int c, float acc) const {
        size_t bt = (size_t)b * Tn + t;
        float ht = tanhf(acc + AX[bt * 1280 + 512 + c]);
        float u  = U[b * 256 + c];
        float h  = (1.0f - u) * hpf[b * 256 + c] + u * ht;
        hnf[b * 256 + c] = h;
        slab_write(Hst, b, c, h);
        slab_write(Hseq, bt, c, h);
    }
};
struct EP_ZPQ {
    const float* AX; __half* P; __half* Q; int t;
    DI void operator()(int b, int col, float acc) const {
        size_t bt = (size_t)b * Tn + t;
        if (col < 256) slab_write(P, b, col, tanhf(acc + AX[bt * 1280 + 768 + col]));
        else           slab_write(Q, b, col - 256, tanhf(acc + AX[bt * 1280 + 1024 + (col - 256)]));
    }
};
struct EP_HEADS {
    float* HD; const float* bias[4];
    DI void operator()(int b, int col, float acc) const {
        int seg = col >> 8, c = col & 255;
        HD[(size_t)b * 1024 + col] = acc + bias[seg][c];
    }
};
struct EP_G {
    float* G; const float* bg;
    DI void operator()(int row, int col, float acc) const {
        G[(size_t)row * 128 + col] = tanhf(acc + bg[col]);
    }
};

// ============================ fp16 2-term split mma.sync GEMM ============================
// CTA tile 64x64; warp tile 16x32 (8 warps as 4m x 2n); MF=1, NF=4.
// K' = 2K (Ahi·Bhi + Alo·Bhi), stage = 64 K-elems = two 32-K sub-chunks.
// 3 stages x 20480 B = 61440 B smem -> 3 CTAs/SM (24 warps). One syncthreads per stage.
constexpr int CHUNK_B = 64 * 80;                 // one 32-K chunk of A or B (5120 B)
constexpr int STG_B   = 4 * CHUNK_B;             // [A0 B0 A1 B1] = 20480 B
constexpr int NSTG    = 3;
constexpr int SMEM_BYTES = NSTG * STG_B;         // 61440

template <class EP>
__global__ __launch_bounds__(256, 3)
void tgemm(ADesc ad, EP ep, const __half* __restrict__ Bp, int K) {
    extern __shared__ __align__(16) uint8_t smem[];
    const uint32_t sb = smem_u32(smem);

    const int tid  = threadIdx.x;
    const int lane = tid & 31;
    const int warp = tid >> 5;
    const int m0 = blockIdx.y * 64;
    const int n0 = blockIdx.x * 64;
    const int nseg = n0 >> 8;
    const int warpM = (warp >> 1) * 16;
    const int warpN = (warp & 1) * 32;
    const int cpt = K >> 5;         // 32-K chunks per split term (even for all K here)
    const int nst = cpt;            // stages: nch/2 = 2*cpt/2

    const __half* const* slabs = (nseg < 2) ? ad.s0 : ad.s1;

    const int frow = tid >> 2;      // 0..63
    const int fq   = tid & 3;       // 16B quarter of the 64B row

    float acc[4][4];
#pragma unroll
    for (int j = 0; j < 4; j++)
#pragma unroll
        for (int q = 0; q < 4; q++) acc[j][q] = 0.0f;

    // fill stage `st` (chunks 2*st, 2*st+1)
    auto fill = [&](int st, int slot) {
#pragma unroll
        for (int sub = 0; sub < 2; sub++) {
            int ch = 2 * st + sub;
            int term = ch >= cpt;           // cpt even -> stages never straddle terms
            int chk = term ? ch - cpt : ch;
            int kk = chk * 32 + fq * 8;
            int slab = kk >> 8, o = kk & 255;
            const __half* srcA = slabs[slab] + (size_t)(m0 + frow) * 512 + term * 256 + o;
            uint32_t base = sb + slot * STG_B + sub * 2 * CHUNK_B;
            cp16(base + frow * 80 + fq * 16, srcA);
            const __half* srcB = Bp + (size_t)(n0 + frow) * K + chk * 32 + fq * 8;
            cp16(base + CHUNK_B + frow * 80 + fq * 16, srcB);
        }
    };

    auto mmastage = [&](int slot) {
#pragma unroll
        for (int sub = 0; sub < 2; sub++) {
            const uint32_t Ab = sb + slot * STG_B + sub * 2 * CHUNK_B;
            const uint32_t Bb = Ab + CHUNK_B;
#pragma unroll
            for (int ks = 0; ks < 2; ks++) {
                uint32_t afr[4];
                ldm_x4(afr, Ab + (warpM + (lane & 15)) * 80 + ((ks << 1) + (lane >> 4)) * 16);
                uint32_t bfr[2][4];
#pragma unroll
                for (int j = 0; j < 2; j++)
                    ldm_x4(bfr[j], Bb + (warpN + j * 16 + (lane & 7) + ((lane >> 4) & 1) * 8) * 80
                                      + ((ks << 1) + ((lane >> 3) & 1)) * 16);
#pragma unroll
                for (int nf = 0; nf < 4; nf++)
                    mma_f16(acc[nf], afr, &bfr[nf >> 1][(nf & 1) * 2]);
            }
        }
    };

    fill(0, 0); CP_COMMIT();
    if (nst > 1) fill(1, 1); CP_COMMIT();

    for (int s = 0; s < nst; s++) {
        if (s + 1 < nst) CP_WAIT(1); else CP_WAIT(0);
        __syncthreads();
        if (s + 2 < nst) fill(s + 2, (s + 2) % NSTG);
        CP_COMMIT();
        mmastage(s % NSTG);
    }

    // register-direct fused epilogue (mma.m16n8k16 C fragment mapping)
#pragma unroll
    for (int nf = 0; nf < 4; nf++)
#pragma unroll
        for (int j = 0; j < 4; j++) {
            int m = m0 + warpM + (lane >> 2) + ((j >> 1) << 3);
            int n = n0 + warpN + (nf >> 1) * 16 + (nf & 1) * 8 + ((lane & 3) << 1) + (j & 1);
            ep(m, n, acc[nf][j]);
        }
}

// ============================ fused weight prep ============================
struct PrepSrc { const float* w[10]; }; // Wr,Wu,Wh,Wzp,Wzq,Wpm,Wps,Wqm,Wqs,Wg

__global__ void prep_all(PrepSrc ps, __half* __restrict__ dst) {
    struct S { int si, sld, sr0; size_t doff; int dr0, K, N; };
    const S tab[15] = {
        {0, 256,   0, O1,    0, 256, 256}, {1, 256,   0, O1,  256, 256, 256},
        {2, 256,   0, O1,  512, 256, 256}, {3, 256,   0, O1,  768, 256, 256},
        {4, 256,   0, O1, 1024, 256, 256},
        {0, 256, 256, O2,    0, 512, 256}, {1, 256, 256, O2,  256, 512, 256},
        {2, 256, 256, O3,    0, 512, 256},
        {3, 256, 256, O4,    0, 256, 256}, {4, 256, 256, O4,  256, 256, 256},
        {5, 256,   0, O5,    0, 256, 256}, {6, 256,   0, O5,  256, 256, 256},
        {7, 256,   0, O5,  512, 256, 256}, {8, 256,   0, O5,  768, 256, 256},
        {9, 128,   0, O6,    0, 768, 128},
    };
    const int cnt[15] = {65536,65536,65536,65536,65536, 131072,131072, 131072,
                         65536,65536, 65536,65536,65536,65536, 98304};
    int e = blockIdx.x * 256 + threadIdx.x;
    if (e >= 1212416) return;
    int s = 14;
    int base = 0;
#pragma unroll
    for (int i = 0; i < 15; i++) {
        int nb = base + cnt[i];
        if (e < nb) { s = i; break; }
        base = nb;
    }
    const S& t = tab[s];
    int local = e - base;
    int k = local / t.N, n = local % t.N;
    float v = ps.w[t.si][(size_t)(t.sr0 + k) * t.sld + n];
    dst[t.doff + (size_t)(t.dr0 + n) * t.K + k] = __float2half_rn(v);
}

// ============================ small kernels ============================
__global__ void init_copy(const float* __restrict__ x, const float* __restrict__ h0,
                          const float* __restrict__ z0, __half* __restrict__ Xs,
                          float* __restrict__ Hf, __half* __restrict__ Hst,
                          __half* __restrict__ Zst) {
    size_t idx = (size_t)blockIdx.x * blockDim.x + threadIdx.x;
    size_t r = idx >> 8;
    int k = (int)(idx & 255);
    slab_write(Xs, r, k, x[idx]);
    if (idx < (size_t)Bn * Hn) {
        float hv = h0[idx], zv = z0[idx];
        Hf[idx] = hv;
        slab_write(Hst, r, k, hv);
        slab_write(Zst, r, k, zv);
    }
}

__global__ void step_latent(const float* __restrict__ HD, const float* __restrict__ eps_t,
                            __half* __restrict__ Zst, __half* __restrict__ Zseq,
                            float* __restrict__ outKL, int t) {
    int b = blockIdx.x, c = threadIdx.x;
    size_t hb = (size_t)b * 1024;
    float mup = HD[hb + c];
    float lp  = HD[hb + 256 + c];
    float muq = HD[hb + 512 + c];
    float lq  = HD[hb + 768 + c];
    float z = muq + expf(0.5f * lq) * eps_t[b * 256 + c];
    size_t bt = (size_t)b * Tn + t;
    slab_write(Zst, b, c, z);
    slab_write(Zseq, bt, c, z);
    float d = muq - mup;
    float kl = 0.5f * (lp - lq) + (expf(lq) + d * d) / (2.0f * expf(lp)) - 0.5f;

    __shared__ float red[8];
    for (int o = 16; o; o >>= 1) kl += __shfl_down_sync(0xffffffffu, kl, o);
    if ((threadIdx.x & 31) == 0) red[threadIdx.x >> 5] = kl;
    __syncthreads();
    if (threadIdx.x == 0) {
        float s = 0.0f;
#pragma unroll
        for (int i = 0; i < 8; i++) s += red[i];
        outKL[bt] = s;
    }
}

__global__ void yhead(const float* __restrict__ G, const float* __restrict__ Wy,
                      const float* __restrict__ by, float* __restrict__ outY) {
    int r = blockIdx.x * 8 + (threadIdx.x >> 5);
    int lane = threadIdx.x & 31;
    float s0 = 0.0f, s1 = 0.0f;
    const float* g = G + (size_t)r * 128;
    for (int k = lane; k < 128; k += 32) {
        float gv = g[k];
        s0 += gv * Wy[k * 2];
        s1 += gv * Wy[k * 2 + 1];
    }
    for (int o = 16; o; o >>= 1) {
        s0 += __shfl_down_sync(0xffffffffu, s0, o);
        s1 += __shfl_down_sync(0xffffffffu, s1, o);
    }
    if (lane == 0) {
        float l0 = s0 + by[0], l1 = s1 + by[1];
        float m = fmaxf(l0, l1);
        float e0 = expf(l0 - m), e1 = expf(l1 - m);
        float inv = 1.0f / (e0 + e1);
        outY[(size_t)r * 2]     = e0 * inv;
        outY[(size_t)r * 2 + 1] = e1 * inv;
    }
}

__global__ void gatherGT(const float* __restrict__ G, const int* __restrict__ Tph,
                         float* __restrict__ outGT) {
    int b = blockIdx.x;
    int t = Tph[b] - 1;
    outGT[(size_t)b * Gn + threadIdx.x] = G[((size_t)b * Tn + t) * Gn + threadIdx.x];
}

// ============================ launch ============================
extern "C" void kernel_launch(void* const* d_in, const int* in_sizes, int n_in,
                              void* d_out, int out_size) {
    const float* x   = (const float*)d_in[0];
    const float* yph = (const float*)d_in[1];
    const int*   Tph = (const int*)  d_in[2];
    const float* h0  = (const float*)d_in[3];
    const float* z0  = (const float*)d_in[4];
    const float* eps = (const float*)d_in[5];
    const float* Wr  = (const float*)d_in[6];  const float* br  = (const float*)d_in[7];
    const float* Wu  = (const float*)d_in[8];  const float* bu  = (const float*)d_in[9];
    const float* Wh  = (const float*)d_in[10]; const float* bh  = (const float*)d_in[11];
    const float* Wzp = (const float*)d_in[12]; const float* bzp = (const float*)d_in[13];
    const float* Wpm = (const float*)d_in[14]; const float* bpm = (const float*)d_in[15];
    const float* Wps = (const float*)d_in[16]; const float* bps = (const float*)d_in[17];
    const float* Wzq = (const float*)d_in[18]; const float* bzq = (const float*)d_in[19];
    const float* Wqm = (const float*)d_in[20]; const float* bqm = (const float*)d_in[21];
    const float* Wqs = (const float*)d_in[22]; const float* bqs = (const float*)d_in[23];
    const float* Wg  = (const float*)d_in[24]; const float* bg  = (const float*)d_in[25];
    const float* Wy  = (const float*)d_in[26]; const float* by  = (const float*)d_in[27];

    float *AX, *U, *HD, *Hf, *Gb;
    __half *Xs, *Hseq, *Zseq, *Hst, *Zst, *RH, *HZP, *HZQ, *Wp;
    {
        void* p;
        cudaGetSymbolAddress(&p, g_AX);   AX   = (float*)p;
        cudaGetSymbolAddress(&p, g_U);    U    = (float*)p;
        cudaGetSymbolAddress(&p, g_HD);   HD   = (float*)p;
        cudaGetSymbolAddress(&p, g_Hf);   Hf   = (float*)p;
        cudaGetSymbolAddress(&p, g_G);    Gb   = (float*)p;
        cudaGetSymbolAddress(&p, g_Xs);   Xs   = (__half*)p;
        cudaGetSymbolAddress(&p, g_Hseq); Hseq = (__half*)p;
        cudaGetSymbolAddress(&p, g_Zseq); Zseq = (__half*)p;
        cudaGetSymbolAddress(&p, g_Hst);  Hst  = (__half*)p;
        cudaGetSymbolAddress(&p, g_Zst);  Zst  = (__half*)p;
        cudaGetSymbolAddress(&p, g_RH);   RH   = (__half*)p;
        cudaGetSymbolAddress(&p, g_HZP);  HZP  = (__half*)p;
        cudaGetSymbolAddress(&p, g_HZQ);  HZQ  = (__half*)p;
        cudaGetSymbolAddress(&p, g_Wp);   Wp   = (__half*)p;
    }

    cudaFuncSetAttribute((const void*)tgemm<EP_AX>,    cudaFuncAttributeMaxDynamicSharedMemorySize, SMEM_BYTES);
    cudaFuncSetAttribute((const void*)tgemm<EP_RU>,    cudaFuncAttributeMaxDynamicSharedMemorySize, SMEM_BYTES);
    cudaFuncSetAttribute((const void*)tgemm<EP_H>,     cudaFuncAttributeMaxDynamicSharedMemorySize, SMEM_BYTES);
    cudaFuncSetAttribute((const void*)tgemm<EP_ZPQ>,   cudaFuncAttributeMaxDynamicSharedMemorySize, SMEM_BYTES);
    cudaFuncSetAttribute((const void*)tgemm<EP_HEADS>, cudaFuncAttributeMaxDynamicSharedMemorySize, SMEM_BYTES);
    cudaFuncSetAttribute((const void*)tgemm<EP_G>,     cudaFuncAttributeMaxDynamicSharedMemorySize, SMEM_BYTES);

    float* out   = (float*)d_out;
    float* outY  = out;
    float* outKL = out + (size_t)BT * Yn;
    float* outGT = out + (size_t)BT * Yn + BT;

    // ---- single fused weight prep ----
    {
        PrepSrc ps;
        ps.w[0] = Wr; ps.w[1] = Wu; ps.w[2] = Wh; ps.w[3] = Wzp; ps.w[4] = Wzq;
        ps.w[5] = Wpm; ps.w[6] = Wps; ps.w[7] = Wqm; ps.w[8] = Wqs; ps.w[9] = Wg;
        prep_all<<<(1212416 + 255) / 256, 256>>>(ps, Wp);
    }

    init_copy<<<BT, 256>>>(x, h0, z0, Xs, Hf, Hst, Zst);

    dim3 blk(256);

    // phase 1: x-projections  -> N=1280, K=256
    {
        ADesc ad{}; ad.s0[0] = Xs; ad.s1[0] = Xs;
        EP_AX ep;
        ep.AX = AX;
        ep.bias[0] = br; ep.bias[1] = bu; ep.bias[2] = bh; ep.bias[3] = bzp; ep.bias[4] = bzq;
        ep.yph = yph; ep.WzqY = Wzq + 512 * 256;
        tgemm<<<dim3(1280 / 64, BT / 64), blk, SMEM_BYTES>>>(ad, ep, Wp + O1, 256);
    }

    // phase 2: sequential scan
    for (int t = 0; t < Tn; t++) {
        int cur = t & 1, nxt = cur ^ 1;
        const float* hpf = Hf + (size_t)cur * Bn * Hn;
        float* hnf       = Hf + (size_t)nxt * Bn * Hn;
        __half* HstC = Hst + (size_t)cur * Bn * 512;
        __half* HstN = Hst + (size_t)nxt * Bn * 512;
        __half* ZstC = Zst + (size_t)cur * Bn * 512;
        __half* ZstN = Zst + (size_t)nxt * Bn * 512;

        { // gates r,u: A = [h_prev | z_prev], N=512, K=512 -> 512 CTAs
            ADesc ad{}; ad.s0[0] = HstC; ad.s0[1] = ZstC; ad.s1[0] = HstC; ad.s1[1] = ZstC;
            EP_RU ep{AX, hpf, U, RH, t};
            tgemm<<<dim3(512 / 64, Bn / 64), blk, SMEM_BYTES>>>(ad, ep, Wp + O2, 512);
        }
        { // candidate + GRU update: A = [r*h_prev | z_prev], N=256, K=512 -> 256 CTAs
            ADesc ad{}; ad.s0[0] = RH; ad.s0[1] = ZstC; ad.s1[0] = RH; ad.s1[1] = ZstC;
            EP_H ep{AX, U, hpf, hnf, HstN, Hseq, t};
            tgemm<<<dim3(256 / 64, Bn / 64), blk, SMEM_BYTES>>>(ad, ep, Wp + O3, 512);
        }
        { // latent hiddens: A = h_new, N=512, K=256 -> 512 CTAs
            ADesc ad{}; ad.s0[0] = HstN; ad.s1[0] = HstN;
            EP_ZPQ ep{AX, HZP, HZQ, t};
            tgemm<<<dim3(512 / 64, Bn / 64), blk, SMEM_BYTES>>>(ad, ep, Wp + O4, 256);
        }
        { // heads: N=1024, K=256 -> 1024 CTAs; A = HZP segs 0-1, HZQ segs 2-3
            ADesc ad{}; ad.s0[0] = HZP; ad.s1[0] = HZQ;
            EP_HEADS ep;
            ep.HD = HD;
            ep.bias[0] = bpm; ep.bias[1] = bps; ep.bias[2] = bqm; ep.bias[3] = bqs;
            tgemm<<<dim3(1024 / 64, Bn / 64), blk, SMEM_BYTES>>>(ad, ep, Wp + O5, 256);
        }
        step_latent<<<Bn, 256>>>(HD, eps + (size_t)t * Bn * Zn, ZstN, Zseq, outKL, t);
    }

    // phase 3: g = tanh([x|h|z] @ Wg + bg), N=128, K=768
    {
        ADesc ad{}; ad.s0[0] = Xs; ad.s0[1] = Hseq; ad.s0[2] = Zseq;
        ad.s1[0] = Xs; ad.s1[1] = Hseq; ad.s1[2] = Zseq;
        EP_G ep{Gb, bg};
        tgemm<<<dim3(Gn / 64, BT / 64), blk, SMEM_BYTES>>>(ad, ep, Wp + O6, 768);
    }
    yhead<<<BT / 8, 256>>>(Gb, Wy, by, outY);
    gatherGT<<<Bn, Gn>>>(Gb, Tph, outGT);
}

// round 9
// speedup vs baseline: 1.0614x; 1.0614x over previous
#include <cuda_runtime.h>
#include <cuda_fp16.h>
#include <math.h>
#include <cstdint>

// Problem constants (fixed by the dataset)
constexpr int Bn = 4096, Tn = 32, Xn = 256, Hn = 256, Zn = 256, Gn = 128, Yn = 2;
constexpr int BT = Bn * Tn; // 131072

#define DI __device__ __forceinline__

DI uint32_t smem_u32(const void* p) {
    uint32_t a;
    asm("{ .reg .u64 t; cvta.to.shared.u64 t, %1; cvt.u32.u64 %0, t; }" : "=r"(a) : "l"(p));
    return a;
}
DI float sigf(float x) { return 1.0f / (1.0f + expf(-x)); }

DI void ldm_x4(uint32_t r[4], uint32_t addr) {
    asm volatile("ldmatrix.sync.aligned.m8n8.x4.shared.b16 {%0,%1,%2,%3}, [%4];"
                 : "=r"(r[0]), "=r"(r[1]), "=r"(r[2]), "=r"(r[3]) : "r"(addr));
}
DI void mma_f16(float d[4], const uint32_t a[4], const uint32_t b[2]) {
    asm volatile(
        "mma.sync.aligned.m16n8k16.row.col.f32.f16.f16.f32 "
        "{%0,%1,%2,%3}, {%4,%5,%6,%7}, {%8,%9}, {%0,%1,%2,%3};"
        : "+f"(d[0]), "+f"(d[1]), "+f"(d[2]), "+f"(d[3])
        : "r"(a[0]), "r"(a[1]), "r"(a[2]), "r"(a[3]), "r"(b[0]), "r"(b[1]));
}
DI void cp16(uint32_t dst, const void* src) {
    asm volatile("cp.async.cg.shared.global [%0], [%1], 16;" :: "r"(dst), "l"(src));
}
#define CP_COMMIT() asm volatile("cp.async.commit_group;" ::: "memory")
#define CP_WAIT(n)  asm volatile("cp.async.wait_group %0;" :: "n"(n) : "memory")

// write fp32 value as fp16 hi/lo pair into a slab [row][512] = [hi(256)|lo(256)]
DI void slab_write(__half* slab, size_t row, int col, float v) {
    __half h = __float2half_rn(v);
    slab[row * 512 + col]       = h;
    slab[row * 512 + 256 + col] = __float2half_rn(v - __half2float(h));
}

// ============================ static device scratch ============================
// AX is T-MAJOR: [t][4096][1280] so each scan step reads a contiguous block
__device__ float g_AX [131072 * 1280];
__device__ float g_U  [4096 * 256];
__device__ float g_HD [4096 * 1024];            // [mu_p | lp | mu_q | lq]
__device__ float g_Hf [2 * 4096 * 256];         // f32 h state (prev/next)
__device__ float g_G  [131072 * 128];
// fp16 hi/lo slabs: [row][512] = [hi|lo]
__device__ __align__(16) __half g_Xs  [(size_t)131072 * 512];
__device__ __align__(16) __half g_Hseq[(size_t)131072 * 512];
__device__ __align__(16) __half g_Zseq[(size_t)131072 * 512];
__device__ __align__(16) __half g_Hst [2 * 4096 * 512];
__device__ __align__(16) __half g_Zst [2 * 4096 * 512];
__device__ __align__(16) __half g_RH  [4096 * 512];
__device__ __align__(16) __half g_HZP [4096 * 512];
__device__ __align__(16) __half g_HZQ [4096 * 512];
// prepacked weights: fp16 hi only, transposed, [N][K] K-major
constexpr size_t O1 = 0;                  // [1280][256]
constexpr size_t O2 = O1 + 1280 * 256;    // [512][512]
constexpr size_t O3 = O2 + 512 * 512;     // [256][512]
constexpr size_t O4 = O3 + 256 * 512;     // [512][256]
constexpr size_t O5 = O4 + 512 * 256;     // [1024][256]
constexpr size_t O6 = O5 + 1024 * 256;    // [128][768]
constexpr size_t WTOT = O6 + 128 * 768;
__device__ __align__(16) __half g_Wp[WTOT];

// ============================ A descriptor ============================
struct ADesc { const __half* s0[3]; const __half* s1[3]; };

// ============================ Epilogues ============================
struct EP_AX { // phase1: row is BT index (b*32+t); store t-major
    float* AX; const float* bias[5]; const float* yph; const float* WzqY;
    DI void operator()(int row, int col, float acc) const {
        int seg = col >> 8, c = col & 255;
        float v = acc + bias[seg][c];
        if (seg == 4)
            v += yph[(size_t)row * 2] * WzqY[c] + yph[(size_t)row * 2 + 1] * WzqY[256 + c];
        size_t tmaj = ((size_t)(row & 31) * Bn + (row >> 5));
        AX[tmaj * 1280 + col] = v;
    }
};
struct EP_RU { // AXt pre-offset to step t; r -> RH slab (r*h_prev), u -> f32 U
    const float* AXt; const float* hpf; float* U; __half* RH;
    DI void operator()(int b, int col, float acc) const {
        float pre = acc + AXt[(size_t)b * 1280 + col];
        if (col < 256) {
            float r = sigf(pre);
            slab_write(RH, b, col, r * hpf[b * 256 + col]);
        } else {
            U[b * 256 + col - 256] = sigf(pre);
        }
    }
};
struct EP_H {
    const float* AXt; const float* U; const float* hpf; float* hnf;
    __half* Hst; __half* Hseq; int t;
    DI void operator()(int b, int c, float acc) const {
        size_t bt = (size_t)b * Tn + t;
        float ht = tanhf(acc + AXt[(size_t)b * 1280 + 512 + c]);
        float u  = U[b * 256 + c];
        float h  = (1.0f - u) * hpf[b * 256 + c] + u * ht;
        hnf[b * 256 + c] = h;
        slab_write(Hst, b, c, h);
        slab_write(Hseq, bt, c, h);
    }
};
struct EP_ZPQ {
    const float* AXt; __half* P; __half* Q;
    DI void operator()(int b, int col, float acc) const {
        if (col < 256) slab_write(P, b, col, tanhf(acc + AXt[(size_t)b * 1280 + 768 + col]));
        else           slab_write(Q, b, col - 256, tanhf(acc + AXt[(size_t)b * 1280 + 768 + col]));
    }
};
struct EP_HEADS {
    float* HD; const float* bias[4];
    DI void operator()(int b, int col, float acc) const {
        int seg = col >> 8, c = col & 255;
        HD[(size_t)b * 1024 + col] = acc + bias[seg][c];
    }
};
struct EP_G {
    float* G; const float* bg;
    DI void operator()(int row, int col, float acc) const {
        G[(size_t)row * 128 + col] = tanhf(acc + bg[col]);
    }
};

// ============================ fp16 2-term split mma.sync GEMM ============================
// CTA tile 64x128; 8 warps as 2(m) x 4(n); warp tile 32x32 (MF=2, NF=4).
// K' = 2K (Ahi·Bhi + Alo·Bhi). One stage = 64 K = two 32-K sub-chunks.
// 3 stages x 30720 B = 92160 B smem -> 2 CTAs/SM. One __syncthreads per 64-K stage.
constexpr int A_CH = 64 * 80;                    // 5120
constexpr int B_CH = 128 * 80;                   // 10240
constexpr int STG_B = 2 * (A_CH + B_CH);         // 30720
constexpr int NSTG  = 3;
constexpr int SMEM_BYTES = NSTG * STG_B;         // 92160

template <class EP>
__global__ __launch_bounds__(256, 2)
void tgemm(ADesc ad, EP ep, const __half* __restrict__ Bp, int K) {
    extern __shared__ __align__(16) uint8_t smem[];
    const uint32_t sb = smem_u32(smem);

    const int tid  = threadIdx.x;
    const int lane = tid & 31;
    const int warp = tid >> 5;
    const int m0 = blockIdx.y * 64;
    const int n0 = blockIdx.x * 128;
    const int nseg = n0 >> 8;
    const int warpM = (warp >> 2) * 32;
    const int warpN = (warp & 3) * 32;
    const int cpt = K >> 5;         // 32-K chunks per split term (even for all K here)
    const int nst = cpt;            // 64-K stages = 2*cpt chunks / 2

    const __half* const* slabs = (nseg < 2) ? ad.s0 : ad.s1;

    const int frow = tid >> 2;      // 0..63
    const int fq   = tid & 3;       // 16B quarter of the 64B row

    float acc[2][4][4];
#pragma unroll
    for (int i = 0; i < 2; i++)
#pragma unroll
        for (int j = 0; j < 4; j++)
#pragma unroll
            for (int q = 0; q < 4; q++) acc[i][j][q] = 0.0f;

    // fill stage `st` (chunks 2*st, 2*st+1) into smem slot
    auto fill = [&](int st, int slot) {
#pragma unroll
        for (int sub = 0; sub < 2; sub++) {
            int ch = 2 * st + sub;
            int term = ch >= cpt;           // cpt even -> stages never straddle terms
            int chk = term ? ch - cpt : ch;
            uint32_t base = sb + slot * STG_B + sub * (A_CH + B_CH);
            { // A: 64 rows x 64B
                int kk = chk * 32 + fq * 8;
                int slab = kk >> 8, o = kk & 255;
                const __half* srcA = slabs[slab] + (size_t)(m0 + frow) * 512 + term * 256 + o;
                cp16(base + frow * 80 + fq * 16, srcA);
            }
            // B: 128 rows x 64B (two waves)
#pragma unroll
            for (int c = 0; c < 2; c++) {
                int id = c * 256 + tid;
                int row = id >> 2, q = id & 3;
                const __half* srcB = Bp + (size_t)(n0 + row) * K + chk * 32 + q * 8;
                cp16(base + A_CH + row * 80 + q * 16, srcB);
            }
        }
    };

    auto mmastage = [&](int slot) {
#pragma unroll
        for (int sub = 0; sub < 2; sub++) {
            const uint32_t Ab = sb + slot * STG_B + sub * (A_CH + B_CH);
            const uint32_t Bb = Ab + A_CH;
#pragma unroll
            for (int ks = 0; ks < 2; ks++) {
                uint32_t afr[2][4];
#pragma unroll
                for (int mf = 0; mf < 2; mf++)
                    ldm_x4(afr[mf], Ab + (warpM + mf * 16 + (lane & 15)) * 80
                                       + ((ks << 1) + (lane >> 4)) * 16);
                uint32_t bfr[2][4];
#pragma unroll
                for (int j = 0; j < 2; j++)
                    ldm_x4(bfr[j], Bb + (warpN + j * 16 + (lane & 7) + ((lane >> 4) & 1) * 8) * 80
                                      + ((ks << 1) + ((lane >> 3) & 1)) * 16);
#pragma unroll
                for (int mf = 0; mf < 2; mf++)
#pragma unroll
                    for (int nf = 0; nf < 4; nf++)
                        mma_f16(acc[mf][nf], afr[mf], &bfr[nf >> 1][(nf & 1) * 2]);
            }
        }
    };

    fill(0, 0); CP_COMMIT();
    if (nst > 1) fill(1, 1);
    CP_COMMIT();

    for (int s = 0; s < nst; s++) {
        if (s + 1 < nst) CP_WAIT(1); else CP_WAIT(0);
        __syncthreads();
        if (s + 2 < nst) fill(s + 2, (s + 2) % NSTG);
        CP_COMMIT();
        mmastage(s % NSTG);
    }

    // register-direct fused epilogue (mma.m16n8k16 C fragment mapping)
#pragma unroll
    for (int mf = 0; mf < 2; mf++)
#pragma unroll
        for (int nf = 0; nf < 4; nf++)
#pragma unroll
            for (int j = 0; j < 4; j++) {
                int m = m0 + warpM + mf * 16 + (lane >> 2) + ((j >> 1) << 3);
                int n = n0 + warpN + (nf >> 1) * 16 + (nf & 1) * 8 + ((lane & 3) << 1) + (j & 1);
                ep(m, n, acc[mf][nf][j]);
            }
}

// ============================ fused weight prep ============================
struct PrepSrc { const float* w[10]; }; // Wr,Wu,Wh,Wzp,Wzq,Wpm,Wps,Wqm,Wqs,Wg

__global__ void prep_all(PrepSrc ps, __half* __restrict__ dst) {
    struct S { int si, sld, sr0; size_t doff; int dr0, K, N; };
    const S tab[15] = {
        {0, 256,   0, O1,    0, 256, 256}, {1, 256,   0, O1,  256, 256, 256},
        {2, 256,   0, O1,  512, 256, 256}, {3, 256,   0, O1,  768, 256, 256},
        {4, 256,   0, O1, 1024, 256, 256},
        {0, 256, 256, O2,    0, 512, 256}, {1, 256, 256, O2,  256, 512, 256},
        {2, 256, 256, O3,    0, 512, 256},
        {3, 256, 256, O4,    0, 256, 256}, {4, 256, 256, O4,  256, 256, 256},
        {5, 256,   0, O5,    0, 256, 256}, {6, 256,   0, O5,  256, 256, 256},
        {7, 256,   0, O5,  512, 256, 256}, {8, 256,   0, O5,  768, 256, 256},
        {9, 128,   0, O6,    0, 768, 128},
    };
    const int cnt[15] = {65536,65536,65536,65536,65536, 131072,131072, 131072,
                         65536,65536, 65536,65536,65536,65536, 98304};
    int e = blockIdx.x * 256 + threadIdx.x;
    if (e >= 1212416) return;
    int s = 14;
    int base = 0;
#pragma unroll
    for (int i = 0; i < 15; i++) {
        int nb = base + cnt[i];
        if (e < nb) { s = i; break; }
        base = nb;
    }
    const S& t = tab[s];
    int local = e - base;
    int k = local / t.N, n = local % t.N;
    float v = ps.w[t.si][(size_t)(t.sr0 + k) * t.sld + n];
    dst[t.doff + (size_t)(t.dr0 + n) * t.K + k] = __float2half_rn(v);
}

// ============================ small kernels ============================
__global__ void init_copy(const float* __restrict__ x, const float* __restrict__ h0,
                          const float* __restrict__ z0, __half* __restrict__ Xs,
                          float* __restrict__ Hf, __half* __restrict__ Hst,
                          __half* __restrict__ Zst) {
    size_t idx = (size_t)blockIdx.x * blockDim.x + threadIdx.x;
    size_t r = idx >> 8;
    int k = (int)(idx & 255);
    slab_write(Xs, r, k, x[idx]);
    if (idx < (size_t)Bn * Hn) {
        float hv = h0[idx], zv = z0[idx];
        Hf[idx] = hv;
        slab_write(Hst, r, k, hv);
        slab_write(Zst, r, k, zv);
    }
}

__global__ void step_latent(const float* __restrict__ HD, const float* __restrict__ eps_t,
                            __half* __restrict__ Zst, __half* __restrict__ Zseq,
                            float* __restrict__ outKL, int t) {
    int b = blockIdx.x, c = threadIdx.x;
    size_t hb = (size_t)b * 1024;
    float mup = HD[hb + c];
    float lp  = HD[hb + 256 + c];
    float muq = HD[hb + 512 + c];
    float lq  = HD[hb + 768 + c];
    float z = muq + expf(0.5f * lq) * eps_t[b * 256 + c];
    size_t bt = (size_t)b * Tn + t;
    slab_write(Zst, b, c, z);
    slab_write(Zseq, bt, c, z);
    float d = muq - mup;
    float kl = 0.5f * (lp - lq) + (expf(lq) + d * d) / (2.0f * expf(lp)) - 0.5f;

    __shared__ float red[8];
    for (int o = 16; o; o >>= 1) kl += __shfl_down_sync(0xffffffffu, kl, o);
    if ((threadIdx.x & 31) == 0) red[threadIdx.x >> 5] = kl;
    __syncthreads();
    if (threadIdx.x == 0) {
        float s = 0.0f;
#pragma unroll
        for (int i = 0; i < 8; i++) s += red[i];
        outKL[bt] = s;
    }
}

__global__ void yhead(const float* __restrict__ G, const float* __restrict__ Wy,
                      const float* __restrict__ by, float* __restrict__ outY) {
    int r = blockIdx.x * 8 + (threadIdx.x >> 5);
    int lane = threadIdx.x & 31;
    float s0 = 0.0f, s1 = 0.0f;
    const float* g = G + (size_t)r * 128;
    for (int k = lane; k < 128; k += 32) {
        float gv = g[k];
        s0 += gv * Wy[k * 2];
        s1 += gv * Wy[k * 2 + 1];
    }
    for (int o = 16; o; o >>= 1) {
        s0 += __shfl_down_sync(0xffffffffu, s0, o);
        s1 += __shfl_down_sync(0xffffffffu, s1, o);
    }
    if (lane == 0) {
        float l0 = s0 + by[0], l1 = s1 + by[1];
        float m = fmaxf(l0, l1);
        float e0 = expf(l0 - m), e1 = expf(l1 - m);
        float inv = 1.0f / (e0 + e1);
        outY[(size_t)r * 2]     = e0 * inv;
        outY[(size_t)r * 2 + 1] = e1 * inv;
    }
}

__global__ void gatherGT(const float* __restrict__ G, const int* __restrict__ Tph,
                         float* __restrict__ outGT) {
    int b = blockIdx.x;
    int t = Tph[b] - 1;
    outGT[(size_t)b * Gn + threadIdx.x] = G[((size_t)b * Tn + t) * Gn + threadIdx.x];
}

// ============================ launch ============================
extern "C" void kernel_launch(void* const* d_in, const int* in_sizes, int n_in,
                              void* d_out, int out_size) {
    const float* x   = (const float*)d_in[0];
    const float* yph = (const float*)d_in[1];
    const int*   Tph = (const int*)  d_in[2];
    const float* h0  = (const float*)d_in[3];
    const float* z0  = (const float*)d_in[4];
    const float* eps = (const float*)d_in[5];
    const float* Wr  = (const float*)d_in[6];  const float* br  = (const float*)d_in[7];
    const float* Wu  = (const float*)d_in[8];  const float* bu  = (const float*)d_in[9];
    const float* Wh  = (const float*)d_in[10]; const float* bh  = (const float*)d_in[11];
    const float* Wzp = (const float*)d_in[12]; const float* bzp = (const float*)d_in[13];
    const float* Wpm = (const float*)d_in[14]; const float* bpm = (const float*)d_in[15];
    const float* Wps = (const float*)d_in[16]; const float* bps = (const float*)d_in[17];
    const float* Wzq = (const float*)d_in[18]; const float* bzq = (const float*)d_in[19];
    const float* Wqm = (const float*)d_in[20]; const float* bqm = (const float*)d_in[21];
    const float* Wqs = (const float*)d_in[22]; const float* bqs = (const float*)d_in[23];
    const float* Wg  = (const float*)d_in[24]; const float* bg  = (const float*)d_in[25];
    const float* Wy  = (const float*)d_in[26]; const float* by  = (const float*)d_in[27];

    float *AX, *U, *HD, *Hf, *Gb;
    __half *Xs, *Hseq, *Zseq, *Hst, *Zst, *RH, *HZP, *HZQ, *Wp;
    {
        void* p;
        cudaGetSymbolAddress(&p, g_AX);   AX   = (float*)p;
        cudaGetSymbolAddress(&p, g_U);    U    = (float*)p;
        cudaGetSymbolAddress(&p, g_HD);   HD   = (float*)p;
        cudaGetSymbolAddress(&p, g_Hf);   Hf   = (float*)p;
        cudaGetSymbolAddress(&p, g_G);    Gb   = (float*)p;
        cudaGetSymbolAddress(&p, g_Xs);   Xs   = (__half*)p;
        cudaGetSymbolAddress(&p, g_Hseq); Hseq = (__half*)p;
        cudaGetSymbolAddress(&p, g_Zseq); Zseq = (__half*)p;
        cudaGetSymbolAddress(&p, g_Hst);  Hst  = (__half*)p;
        cudaGetSymbolAddress(&p, g_Zst);  Zst  = (__half*)p;
        cudaGetSymbolAddress(&p, g_RH);   RH   = (__half*)p;
        cudaGetSymbolAddress(&p, g_HZP);  HZP  = (__half*)p;
        cudaGetSymbolAddress(&p, g_HZQ);  HZQ  = (__half*)p;
        cudaGetSymbolAddress(&p, g_Wp);   Wp   = (__half*)p;
    }

    cudaFuncSetAttribute((const void*)tgemm<EP_AX>,    cudaFuncAttributeMaxDynamicSharedMemorySize, SMEM_BYTES);
    cudaFuncSetAttribute((const void*)tgemm<EP_RU>,    cudaFuncAttributeMaxDynamicSharedMemorySize, SMEM_BYTES);
    cudaFuncSetAttribute((const void*)tgemm<EP_H>,     cudaFuncAttributeMaxDynamicSharedMemorySize, SMEM_BYTES);
    cudaFuncSetAttribute((const void*)tgemm<EP_ZPQ>,   cudaFuncAttributeMaxDynamicSharedMemorySize, SMEM_BYTES);
    cudaFuncSetAttribute((const void*)tgemm<EP_HEADS>, cudaFuncAttributeMaxDynamicSharedMemorySize, SMEM_BYTES);
    cudaFuncSetAttribute((const void*)tgemm<EP_G>,     cudaFuncAttributeMaxDynamicSharedMemorySize, SMEM_BYTES);

    float* out   = (float*)d_out;
    float* outY  = out;
    float* outKL = out + (size_t)BT * Yn;
    float* outGT = out + (size_t)BT * Yn + BT;

    // ---- single fused weight prep ----
    {
        PrepSrc ps;
        ps.w[0] = Wr; ps.w[1] = Wu; ps.w[2] = Wh; ps.w[3] = Wzp; ps.w[4] = Wzq;
        ps.w[5] = Wpm; ps.w[6] = Wps; ps.w[7] = Wqm; ps.w[8] = Wqs; ps.w[9] = Wg;
        prep_all<<<(1212416 + 255) / 256, 256>>>(ps, Wp);
    }

    init_copy<<<BT, 256>>>(x, h0, z0, Xs, Hf, Hst, Zst);

    dim3 blk(256);

    // phase 1: x-projections  -> N=1280, K=256 (AX stored t-major)
    {
        ADesc ad{}; ad.s0[0] = Xs; ad.s1[0] = Xs;
        EP_AX ep;
        ep.AX = AX;
        ep.bias[0] = br; ep.bias[1] = bu; ep.bias[2] = bh; ep.bias[3] = bzp; ep.bias[4] = bzq;
        ep.yph = yph; ep.WzqY = Wzq + 512 * 256;
        tgemm<<<dim3(1280 / 128, BT / 64), blk, SMEM_BYTES>>>(ad, ep, Wp + O1, 256);
    }

    // phase 2: sequential scan
    for (int t = 0; t < Tn; t++) {
        int cur = t & 1, nxt = cur ^ 1;
        const float* hpf = Hf + (size_t)cur * Bn * Hn;
        float* hnf       = Hf + (size_t)nxt * Bn * Hn;
        __half* HstC = Hst + (size_t)cur * Bn * 512;
        __half* HstN = Hst + (size_t)nxt * Bn * 512;
        __half* ZstC = Zst + (size_t)cur * Bn * 512;
        __half* ZstN = Zst + (size_t)nxt * Bn * 512;
        const float* AXt = AX + (size_t)t * Bn * 1280;

        { // gates r,u: A = [h_prev | z_prev], N=512, K=512 -> 256 CTAs
            ADesc ad{}; ad.s0[0] = HstC; ad.s0[1] = ZstC; ad.s1[0] = HstC; ad.s1[1] = ZstC;
            EP_RU ep{AXt, hpf, U, RH};
            tgemm<<<dim3(512 / 128, Bn / 64), blk, SMEM_BYTES>>>(ad, ep, Wp + O2, 512);
        }
        { // candidate + GRU update: A = [r*h_prev | z_prev], N=256, K=512 -> 128 CTAs
            ADesc ad{}; ad.s0[0] = RH; ad.s0[1] = ZstC; ad.s1[0] = RH; ad.s1[1] = ZstC;
            EP_H ep{AXt, U, hpf, hnf, HstN, Hseq, t};
            tgemm<<<dim3(256 / 128, Bn / 64), blk, SMEM_BYTES>>>(ad, ep, Wp + O3, 512);
        }
        { // latent hiddens: A = h_new, N=512, K=256 -> 256 CTAs
            ADesc ad{}; ad.s0[0] = HstN; ad.s1[0] = HstN;
            EP_ZPQ ep{AXt, HZP, HZQ};
            tgemm<<<dim3(512 / 128, Bn / 64), blk, SMEM_BYTES>>>(ad, ep, Wp + O4, 256);
        }
        { // heads: N=1024, K=256 -> 512 CTAs; A = HZP segs 0-1, HZQ segs 2-3
            ADesc ad{}; ad.s0[0] = HZP; ad.s1[0] = HZQ;
            EP_HEADS ep;
            ep.HD = HD;
            ep.bias[0] = bpm; ep.bias[1] = bps; ep.bias[2] = bqm; ep.bias[3] = bqs;
            tgemm<<<dim3(1024 / 128, Bn / 64), blk, SMEM_BYTES>>>(ad, ep, Wp + O5, 256);
        }
        step_latent<<<Bn, 256>>>(HD, eps + (size_t)t * Bn * Zn, ZstN, Zseq, outKL, t);
    }

    // phase 3: g = tanh([x|h|z] @ Wg + bg), N=128, K=768
    {
        ADesc ad{}; ad.s0[0] = Xs; ad.s0[1] = Hseq; ad.s0[2] = Zseq;
        ad.s1[0] = Xs; ad.s1[1] = Hseq; ad.s1[2] = Zseq;
        EP_G ep{Gb, bg};
        tgemm<<<dim3(Gn / 128, BT / 64), blk, SMEM_BYTES>>>(ad, ep, Wp + O6, 768);
    }
    yhead<<<BT / 8, 256>>>(Gb, Wy, by, outY);
    gatherGT<<<Bn, Gn>>>(Gb, Tph, outGT);
}

// round 10
// speedup vs baseline: 1.1279x; 1.0626x over previous
#include <cuda_runtime.h>
#include <cuda_fp16.h>
#include <math.h>
#include <cstdint>

// Problem constants (fixed by the dataset)
constexpr int Bn = 4096, Tn = 32, Xn = 256, Hn = 256, Zn = 256, Gn = 128, Yn = 2;
constexpr int BT = Bn * Tn; // 131072

#define DI __device__ __forceinline__

DI uint32_t smem_u32(const void* p) {
    uint32_t a;
    asm("{ .reg .u64 t; cvta.to.shared.u64 t, %1; cvt.u32.u64 %0, t; }" : "=r"(a) : "l"(p));
    return a;
}
DI float sigf(float x) { return 1.0f / (1.0f + expf(-x)); }

DI void ldm_x4(uint32_t r[4], uint32_t addr) {
    asm volatile("ldmatrix.sync.aligned.m8n8.x4.shared.b16 {%0,%1,%2,%3}, [%4];"
                 : "=r"(r[0]), "=r"(r[1]), "=r"(r[2]), "=r"(r[3]) : "r"(addr));
}
DI void mma_f16(float d[4], const uint32_t a[4], const uint32_t b[2]) {
    asm volatile(
        "mma.sync.aligned.m16n8k16.row.col.f32.f16.f16.f32 "
        "{%0,%1,%2,%3}, {%4,%5,%6,%7}, {%8,%9}, {%0,%1,%2,%3};"
        : "+f"(d[0]), "+f"(d[1]), "+f"(d[2]), "+f"(d[3])
        : "r"(a[0]), "r"(a[1]), "r"(a[2]), "r"(a[3]), "r"(b[0]), "r"(b[1]));
}
DI void cp16(uint32_t dst, const void* src) {
    asm volatile("cp.async.cg.shared.global [%0], [%1], 16;" :: "r"(dst), "l"(src));
}
#define CP_COMMIT() asm volatile("cp.async.commit_group;" ::: "memory")
#define CP_WAIT(n)  asm volatile("cp.async.wait_group %0;" :: "n"(n) : "memory")

// write fp32 value as fp16 hi/lo pair into a slab [row][512] = [hi(256)|lo(256)]
DI void slab_write(__half* slab, size_t row, int col, float v) {
    __half h = __float2half_rn(v);
    slab[row * 512 + col]       = h;
    slab[row * 512 + 256 + col] = __float2half_rn(v - __half2float(h));
}

// ============================ static device scratch ============================
// AX is T-MAJOR: [t][4096][1280] so each scan step reads a contiguous 21MB block
__device__ float g_AX [131072 * 1280];
__device__ float g_U  [4096 * 256];
__device__ float g_HD [4096 * 1024];            // [mu_p | lp | mu_q | lq]
__device__ float g_Hf [2 * 4096 * 256];         // f32 h state (prev/next)
__device__ float g_G  [131072 * 128];
// fp16 hi/lo slabs: [row][512] = [hi|lo]
__device__ __align__(16) __half g_Xs  [(size_t)131072 * 512];
__device__ __align__(16) __half g_Hseq[(size_t)131072 * 512];
__device__ __align__(16) __half g_Zseq[(size_t)131072 * 512];
__device__ __align__(16) __half g_Hst [2 * 4096 * 512];
__device__ __align__(16) __half g_Zst [2 * 4096 * 512];
__device__ __align__(16) __half g_RH  [4096 * 512];
__device__ __align__(16) __half g_HZP [4096 * 512];
__device__ __align__(16) __half g_HZQ [4096 * 512];
// prepacked weights: fp16 hi only, transposed, [N][K] K-major
constexpr size_t O1 = 0;                  // [1280][256]
constexpr size_t O2 = O1 + 1280 * 256;    // [512][512]
constexpr size_t O3 = O2 + 512 * 512;     // [256][512]
constexpr size_t O4 = O3 + 256 * 512;     // [512][256]
constexpr size_t O5 = O4 + 512 * 256;     // [1024][256]
constexpr size_t O6 = O5 + 1024 * 256;    // [128][768]
constexpr size_t WTOT = O6 + 128 * 768;
__device__ __align__(16) __half g_Wp[WTOT];

// ============================ A descriptor ============================
struct ADesc { const __half* s0[3]; const __half* s1[3]; };

// ============================ Epilogues ============================
struct EP_AX { // phase1: row is BT index (b*32+t); store t-major
    float* AX; const float* bias[5]; const float* yph; const float* WzqY;
    DI void operator()(int row, int col, float acc) const {
        int seg = col >> 8, c = col & 255;
        float v = acc + bias[seg][c];
        if (seg == 4)
            v += yph[(size_t)row * 2] * WzqY[c] + yph[(size_t)row * 2 + 1] * WzqY[256 + c];
        size_t tmaj = ((size_t)(row & 31) * Bn + (row >> 5));
        AX[tmaj * 1280 + col] = v;
    }
};
struct EP_RU { // AXt pre-offset to step t; r -> RH slab (r*h_prev), u -> f32 U
    const float* AXt; const float* hpf; float* U; __half* RH;
    DI void operator()(int b, int col, float acc) const {
        float pre = acc + AXt[(size_t)b * 1280 + col];
        if (col < 256) {
            float r = sigf(pre);
            slab_write(RH, b, col, r * hpf[b * 256 + col]);
        } else {
            U[b * 256 + col - 256] = sigf(pre);
        }
    }
};
struct EP_H {
    const float* AXt; const float* U; const float* hpf; float* hnf;
    __half* Hst; __half* Hseq; int t;
    DI void operator()(int b, int c, float acc) const {
        size_t bt = (size_t)b * Tn + t;
        float ht = tanhf(acc + AXt[(size_t)b * 1280 + 512 + c]);
        float u  = U[b * 256 + c];
        float h  = (1.0f - u) * hpf[b * 256 + c] + u * ht;
        hnf[b * 256 + c] = h;
        slab_write(Hst, b, c, h);
        slab_write(Hseq, bt, c, h);
    }
};
struct EP_ZPQ {
    const float* AXt; __half* P; __half* Q;
    DI void operator()(int b, int col, float acc) const {
        if (col < 256) slab_write(P, b, col, tanhf(acc + AXt[(size_t)b * 1280 + 768 + col]));
        else           slab_write(Q, b, col - 256, tanhf(acc + AXt[(size_t)b * 1280 + 768 + col]));
    }
};
struct EP_HEADS {
    float* HD; const float* bias[4];
    DI void operator()(int b, int col, float acc) const {
        int seg = col >> 8, c = col & 255;
        HD[(size_t)b * 1024 + col] = acc + bias[seg][c];
    }
};
struct EP_G {
    float* G; const float* bg;
    DI void operator()(int row, int col, float acc) const {
        G[(size_t)row * 128 + col] = tanhf(acc + bg[col]);
    }
};

// ============================ fp16 2-term split mma.sync GEMM ============================
// R7 config at higher occupancy: CTA tile 64x128; 8 warps 2(m) x 4(n); warp tile 32x32.
// K' = 2K (Ahi·Bhi + Alo·Bhi), 32-K chunks, 4 stages x 15360 B = 61440 B -> 3 CTAs/SM.
constexpr int A_CH = 64 * 80;                    // 5120
constexpr int B_CH = 128 * 80;                   // 10240
constexpr int STG_B = A_CH + B_CH;               // 15360
constexpr int NSTG  = 4;
constexpr int SMEM_BYTES = NSTG * STG_B;         // 61440

template <class EP>
__global__ __launch_bounds__(256, 3)
void tgemm(ADesc ad, EP ep, const __half* __restrict__ Bp, int K) {
    extern __shared__ __align__(16) uint8_t smem[];
    const uint32_t sb = smem_u32(smem);

    const int tid  = threadIdx.x;
    const int lane = tid & 31;
    const int warp = tid >> 5;
    const int m0 = blockIdx.y * 64;
    const int n0 = blockIdx.x * 128;
    const int nseg = n0 >> 8;
    const int warpM = (warp >> 2) * 32;
    const int warpN = (warp & 3) * 32;
    const int cpt = K >> 5;         // 32-K chunks per split term
    const int nch = 2 * cpt;

    const __half* const* slabs = (nseg < 2) ? ad.s0 : ad.s1;

    const int frow = tid >> 2;      // 0..63
    const int fq   = tid & 3;       // 16B quarter of the 64B row

    float acc[2][4][4];
#pragma unroll
    for (int i = 0; i < 2; i++)
#pragma unroll
        for (int j = 0; j < 4; j++)
#pragma unroll
            for (int q = 0; q < 4; q++) acc[i][j][q] = 0.0f;

    auto fill = [&](int ch, int slot) {
        int term = ch >= cpt;
        int chk = term ? ch - cpt : ch;
        uint32_t base = sb + slot * STG_B;
        { // A: 64 rows x 64B
            int kk = chk * 32 + fq * 8;
            int slab = kk >> 8, o = kk & 255;
            const __half* srcA = slabs[slab] + (size_t)(m0 + frow) * 512 + term * 256 + o;
            cp16(base + frow * 80 + fq * 16, srcA);
        }
        // B: 128 rows x 64B (two waves)
#pragma unroll
        for (int c = 0; c < 2; c++) {
            int id = c * 256 + tid;
            int row = id >> 2, q = id & 3;
            const __half* srcB = Bp + (size_t)(n0 + row) * K + chk * 32 + q * 8;
            cp16(base + A_CH + row * 80 + q * 16, srcB);
        }
    };

    auto mmastep = [&](int slot) {
        const uint32_t Ab = sb + slot * STG_B;
        const uint32_t Bb = Ab + A_CH;
#pragma unroll
        for (int ks = 0; ks < 2; ks++) {
            uint32_t afr[2][4];
#pragma unroll
            for (int mf = 0; mf < 2; mf++)
                ldm_x4(afr[mf], Ab + (warpM + mf * 16 + (lane & 15)) * 80
                                   + ((ks << 1) + (lane >> 4)) * 16);
            uint32_t bfr[2][4];
#pragma unroll
            for (int j = 0; j < 2; j++)
                ldm_x4(bfr[j], Bb + (warpN + j * 16 + (lane & 7) + ((lane >> 4) & 1) * 8) * 80
                                  + ((ks << 1) + ((lane >> 3) & 1)) * 16);
#pragma unroll
            for (int mf = 0; mf < 2; mf++)
#pragma unroll
                for (int nf = 0; nf < 4; nf++)
                    mma_f16(acc[mf][nf], afr[mf], &bfr[nf >> 1][(nf & 1) * 2]);
        }
    };

    // prologue: NSTG-1 = 3 chunks in flight
#pragma unroll
    for (int ch = 0; ch < NSTG - 1; ch++) {
        if (ch < nch) fill(ch, ch);
        CP_COMMIT();
    }

    for (int i = 0; i < nch; i++) {
        CP_WAIT(NSTG - 2);
        __syncthreads();
        if (i + NSTG - 1 < nch) fill(i + NSTG - 1, (i + NSTG - 1) % NSTG);
        CP_COMMIT();
        mmastep(i % NSTG);
    }

    // register-direct fused epilogue (mma.m16n8k16 C fragment mapping)
#pragma unroll
    for (int mf = 0; mf < 2; mf++)
#pragma unroll
        for (int nf = 0; nf < 4; nf++)
#pragma unroll
            for (int j = 0; j < 4; j++) {
                int m = m0 + warpM + mf * 16 + (lane >> 2) + ((j >> 1) << 3);
                int n = n0 + warpN + (nf >> 1) * 16 + (nf & 1) * 8 + ((lane & 3) << 1) + (j & 1);
                ep(m, n, acc[mf][nf][j]);
            }
}

// ============================ fused weight prep ============================
struct PrepSrc { const float* w[10]; }; // Wr,Wu,Wh,Wzp,Wzq,Wpm,Wps,Wqm,Wqs,Wg

__global__ void prep_all(PrepSrc ps, __half* __restrict__ dst) {
    struct S { int si, sld, sr0; size_t doff; int dr0, K, N; };
    const S tab[15] = {
        {0, 256,   0, O1,    0, 256, 256}, {1, 256,   0, O1,  256, 256, 256},
        {2, 256,   0, O1,  512, 256, 256}, {3, 256,   0, O1,  768, 256, 256},
        {4, 256,   0, O1, 1024, 256, 256},
        {0, 256, 256, O2,    0, 512, 256}, {1, 256, 256, O2,  256, 512, 256},
        {2, 256, 256, O3,    0, 512, 256},
        {3, 256, 256, O4,    0, 256, 256}, {4, 256, 256, O4,  256, 256, 256},
        {5, 256,   0, O5,    0, 256, 256}, {6, 256,   0, O5,  256, 256, 256},
        {7, 256,   0, O5,  512, 256, 256}, {8, 256,   0, O5,  768, 256, 256},
        {9, 128,   0, O6,    0, 768, 128},
    };
    const int cnt[15] = {65536,65536,65536,65536,65536, 131072,131072, 131072,
                         65536,65536, 65536,65536,65536,65536, 98304};
    int e = blockIdx.x * 256 + threadIdx.x;
    if (e >= 1212416) return;
    int s = 14;
    int base = 0;
#pragma unroll
    for (int i = 0; i < 15; i++) {
        int nb = base + cnt[i];
        if (e < nb) { s = i; break; }
        base = nb;
    }
    const S& t = tab[s];
    int local = e - base;
    int k = local / t.N, n = local % t.N;
    float v = ps.w[t.si][(size_t)(t.sr0 + k) * t.sld + n];
    dst[t.doff + (size_t)(t.dr0 + n) * t.K + k] = __float2half_rn(v);
}

// ============================ small kernels ============================
__global__ void init_copy(const float* __restrict__ x, const float* __restrict__ h0,
                          const float* __restrict__ z0, __half* __restrict__ Xs,
                          float* __restrict__ Hf, __half* __restrict__ Hst,
                          __half* __restrict__ Zst) {
    size_t idx = (size_t)blockIdx.x * blockDim.x + threadIdx.x;
    size_t r = idx >> 8;
    int k = (int)(idx & 255);
    slab_write(Xs, r, k, x[idx]);
    if (idx < (size_t)Bn * Hn) {
        float hv = h0[idx], zv = z0[idx];
        Hf[idx] = hv;
        slab_write(Hst, r, k, hv);
        slab_write(Zst, r, k, zv);
    }
}

__global__ void step_latent(const float* __restrict__ HD, const float* __restrict__ eps_t,
                            __half* __restrict__ Zst, __half* __restrict__ Zseq,
                            float* __restrict__ outKL, int t) {
    int b = blockIdx.x, c = threadIdx.x;
    size_t hb = (size_t)b * 1024;
    float mup = HD[hb + c];
    float lp  = HD[hb + 256 + c];
    float muq = HD[hb + 512 + c];
    float lq  = HD[hb + 768 + c];
    float z = muq + expf(0.5f * lq) * eps_t[b * 256 + c];
    size_t bt = (size_t)b * Tn + t;
    slab_write(Zst, b, c, z);
    slab_write(Zseq, bt, c, z);
    float d = muq - mup;
    float kl = 0.5f * (lp - lq) + (expf(lq) + d * d) / (2.0f * expf(lp)) - 0.5f;

    __shared__ float red[8];
    for (int o = 16; o; o >>= 1) kl += __shfl_down_sync(0xffffffffu, kl, o);
    if ((threadIdx.x & 31) == 0) red[threadIdx.x >> 5] = kl;
    __syncthreads();
    if (threadIdx.x == 0) {
        float s = 0.0f;
#pragma unroll
        for (int i = 0; i < 8; i++) s += red[i];
        outKL[bt] = s;
    }
}

__global__ void yhead(const float* __restrict__ G, const float* __restrict__ Wy,
                      const float* __restrict__ by, float* __restrict__ outY) {
    int r = blockIdx.x * 8 + (threadIdx.x >> 5);
    int lane = threadIdx.x & 31;
    float s0 = 0.0f, s1 = 0.0f;
    const float* g = G + (size_t)r * 128;
    for (int k = lane; k < 128; k += 32) {
        float gv = g[k];
        s0 += gv * Wy[k * 2];
        s1 += gv * Wy[k * 2 + 1];
    }
    for (int o = 16; o; o >>= 1) {
        s0 += __shfl_down_sync(0xffffffffu, s0, o);
        s1 += __shfl_down_sync(0xffffffffu, s1, o);
    }
    if (lane == 0) {
        float l0 = s0 + by[0], l1 = s1 + by[1];
        float m = fmaxf(l0, l1);
        float e0 = expf(l0 - m), e1 = expf(l1 - m);
        float inv = 1.0f / (e0 + e1);
        outY[(size_t)r * 2]     = e0 * inv;
        outY[(size_t)r * 2 + 1] = e1 * inv;
    }
}

__global__ void gatherGT(const float* __restrict__ G, const int* __restrict__ Tph,
                         float* __restrict__ outGT) {
    int b = blockIdx.x;
    int t = Tph[b] - 1;
    outGT[(size_t)b * Gn + threadIdx.x] = G[((size_t)b * Tn + t) * Gn + threadIdx.x];
}

// ============================ launch ============================
extern "C" void kernel_launch(void* const* d_in, const int* in_sizes, int n_in,
                              void* d_out, int out_size) {
    const float* x   = (const float*)d_in[0];
    const float* yph = (const float*)d_in[1];
    const int*   Tph = (const int*)  d_in[2];
    const float* h0  = (const float*)d_in[3];
    const float* z0  = (const float*)d_in[4];
    const float* eps = (const float*)d_in[5];
    const float* Wr  = (const float*)d_in[6];  const float* br  = (const float*)d_in[7];
    const float* Wu  = (const float*)d_in[8];  const float* bu  = (const float*)d_in[9];
    const float* Wh  = (const float*)d_in[10]; const float* bh  = (const float*)d_in[11];
    const float* Wzp = (const float*)d_in[12]; const float* bzp = (const float*)d_in[13];
    const float* Wpm = (const float*)d_in[14]; const float* bpm = (const float*)d_in[15];
    const float* Wps = (const float*)d_in[16]; const float* bps = (const float*)d_in[17];
    const float* Wzq = (const float*)d_in[18]; const float* bzq = (const float*)d_in[19];
    const float* Wqm = (const float*)d_in[20]; const float* bqm = (const float*)d_in[21];
    const float* Wqs = (const float*)d_in[22]; const float* bqs = (const float*)d_in[23];
    const float* Wg  = (const float*)d_in[24]; const float* bg  = (const float*)d_in[25];
    const float* Wy  = (const float*)d_in[26]; const float* by  = (const float*)d_in[27];

    float *AX, *U, *HD, *Hf, *Gb;
    __half *Xs, *Hseq, *Zseq, *Hst, *Zst, *RH, *HZP, *HZQ, *Wp;
    {
        void* p;
        cudaGetSymbolAddress(&p, g_AX);   AX   = (float*)p;
        cudaGetSymbolAddress(&p, g_U);    U    = (float*)p;
        cudaGetSymbolAddress(&p, g_HD);   HD   = (float*)p;
        cudaGetSymbolAddress(&p, g_Hf);   Hf   = (float*)p;
        cudaGetSymbolAddress(&p, g_G);    Gb   = (float*)p;
        cudaGetSymbolAddress(&p, g_Xs);   Xs   = (__half*)p;
        cudaGetSymbolAddress(&p, g_Hseq); Hseq = (__half*)p;
        cudaGetSymbolAddress(&p, g_Zseq); Zseq = (__half*)p;
        cudaGetSymbolAddress(&p, g_Hst);  Hst  = (__half*)p;
        cudaGetSymbolAddress(&p, g_Zst);  Zst  = (__half*)p;
        cudaGetSymbolAddress(&p, g_RH);   RH   = (__half*)p;
        cudaGetSymbolAddress(&p, g_HZP);  HZP  = (__half*)p;
        cudaGetSymbolAddress(&p, g_HZQ);  HZQ  = (__half*)p;
        cudaGetSymbolAddress(&p, g_Wp);   Wp   = (__half*)p;
    }

    cudaFuncSetAttribute((const void*)tgemm<EP_AX>,    cudaFuncAttributeMaxDynamicSharedMemorySize, SMEM_BYTES);
    cudaFuncSetAttribute((const void*)tgemm<EP_RU>,    cudaFuncAttributeMaxDynamicSharedMemorySize, SMEM_BYTES);
    cudaFuncSetAttribute((const void*)tgemm<EP_H>,     cudaFuncAttributeMaxDynamicSharedMemorySize, SMEM_BYTES);
    cudaFuncSetAttribute((const void*)tgemm<EP_ZPQ>,   cudaFuncAttributeMaxDynamicSharedMemorySize, SMEM_BYTES);
    cudaFuncSetAttribute((const void*)tgemm<EP_HEADS>, cudaFuncAttributeMaxDynamicSharedMemorySize, SMEM_BYTES);
    cudaFuncSetAttribute((const void*)tgemm<EP_G>,     cudaFuncAttributeMaxDynamicSharedMemorySize, SMEM_BYTES);

    float* out   = (float*)d_out;
    float* outY  = out;
    float* outKL = out + (size_t)BT * Yn;
    float* outGT = out + (size_t)BT * Yn + BT;

    // ---- single fused weight prep ----
    {
        PrepSrc ps;
        ps.w[0] = Wr; ps.w[1] = Wu; ps.w[2] = Wh; ps.w[3] = Wzp; ps.w[4] = Wzq;
        ps.w[5] = Wpm; ps.w[6] = Wps; ps.w[7] = Wqm; ps.w[8] = Wqs; ps.w[9] = Wg;
        prep_all<<<(1212416 + 255) / 256, 256>>>(ps, Wp);
    }

    init_copy<<<BT, 256>>>(x, h0, z0, Xs, Hf, Hst, Zst);

    dim3 blk(256);

    // phase 1: x-projections  -> N=1280, K=256 (AX stored t-major)
    {
        ADesc ad{}; ad.s0[0] = Xs; ad.s1[0] = Xs;
        EP_AX ep;
        ep.AX = AX;
        ep.bias[0] = br; ep.bias[1] = bu; ep.bias[2] = bh; ep.bias[3] = bzp; ep.bias[4] = bzq;
        ep.yph = yph; ep.WzqY = Wzq + 512 * 256;
        tgemm<<<dim3(1280 / 128, BT / 64), blk, SMEM_BYTES>>>(ad, ep, Wp + O1, 256);
    }

    // phase 2: sequential scan
    for (int t = 0; t < Tn; t++) {
        int cur = t & 1, nxt = cur ^ 1;
        const float* hpf = Hf + (size_t)cur * Bn * Hn;
        float* hnf       = Hf + (size_t)nxt * Bn * Hn;
        __half* HstC = Hst + (size_t)cur * Bn * 512;
        __half* HstN = Hst + (size_t)nxt * Bn * 512;
        __half* ZstC = Zst + (size_t)cur * Bn * 512;
        __half* ZstN = Zst + (size_t)nxt * Bn * 512;
        const float* AXt = AX + (size_t)t * Bn * 1280;

        { // gates r,u: A = [h_prev | z_prev], N=512, K=512 -> 256 CTAs
            ADesc ad{}; ad.s0[0] = HstC; ad.s0[1] = ZstC; ad.s1[0] = HstC; ad.s1[1] = ZstC;
            EP_RU ep{AXt, hpf, U, RH};
            tgemm<<<dim3(512 / 128, Bn / 64), blk, SMEM_BYTES>>>(ad, ep, Wp + O2, 512);
        }
        { // candidate + GRU update: A = [r*h_prev | z_prev], N=256, K=512 -> 128 CTAs
            ADesc ad{}; ad.s0[0] = RH; ad.s0[1] = ZstC; ad.s1[0] = RH; ad.s1[1] = ZstC;
            EP_H ep{AXt, U, hpf, hnf, HstN, Hseq, t};
            tgemm<<<dim3(256 / 128, Bn / 64), blk, SMEM_BYTES>>>(ad, ep, Wp + O3, 512);
        }
        { // latent hiddens: A = h_new, N=512, K=256 -> 256 CTAs
            ADesc ad{}; ad.s0[0] = HstN; ad.s1[0] = HstN;
            EP_ZPQ ep{AXt, HZP, HZQ};
            tgemm<<<dim3(512 / 128, Bn / 64), blk, SMEM_BYTES>>>(ad, ep, Wp + O4, 256);
        }
        { // heads: N=1024, K=256 -> 512 CTAs; A = HZP segs 0-1, HZQ segs 2-3
            ADesc ad{}; ad.s0[0] = HZP; ad.s1[0] = HZQ;
            EP_HEADS ep;
            ep.HD = HD;
            ep.bias[0] = bpm; ep.bias[1] = bps; ep.bias[2] = bqm; ep.bias[3] = bqs;
            tgemm<<<dim3(1024 / 128, Bn / 64), blk, SMEM_BYTES>>>(ad, ep, Wp + O5, 256);
        }
        step_latent<<<Bn, 256>>>(HD, eps + (size_t)t * Bn * Zn, ZstN, Zseq, outKL, t);
    }

    // phase 3: g = tanh([x|h|z] @ Wg + bg), N=128, K=768
    {
        ADesc ad{}; ad.s0[0] = Xs; ad.s0[1] = Hseq; ad.s0[2] = Zseq;
        ad.s1[0] = Xs; ad.s1[1] = Hseq; ad.s1[2] = Zseq;
        EP_G ep{Gb, bg};
        tgemm<<<dim3(Gn / 128, BT / 64), blk, SMEM_BYTES>>>(ad, ep, Wp + O6, 768);
    }
    yhead<<<BT / 8, 256>>>(Gb, Wy, by, outY);
    gatherGT<<<Bn, Gn>>>(Gb, Tph, outGT);
}